// round 15
// baseline (speedup 1.0000x reference)
#include <cuda_runtime.h>
#include <cuda_fp16.h>
#include <cstdint>

// Problem constants
#define B_  32
#define T_  1024
#define I_  512
#define H_  512
#define M_  (B_*T_)          // 32768
#define KD_ 1024             // 2*I
#define ND_ 1024             // 2*H (n<512: f gate, n>=512: z gate)

#define CHUNKS 16
#define CLEN   (T_/CHUNKS)   // 64

// GEMM tiling (fp16, shared-window): BM=128, BN=128, window K=512, BK=32/stage
#define BM 128
#define BN 128
#define BK 32
#define STAGES 4
#define STG_A 8448           // 132 rows x 64B (129 used: X[m0-1 .. m0+127])
#define STG_B 16384          // 2 taps x 128 rows x 64B
#define STG_BYTES (STG_A + STG_B)   // 24832
#define NKT (I_/BK)          // 16 k-steps over the 512 window

// ---------------- scratch (static __device__, allocation-free) ----------------
__device__ __align__(128) __half g_bmath[ND_ * KD_];        // [n][tap*512+i] halfs, 2 MB
__device__ __align__(128) __half g_xh[(size_t)M_ * I_];     // fp16 copy of X, 34 MB
__device__ float g_bias[ND_];
__device__ __align__(128) __half g_rawh[(size_t)M_ * ND_];  // 67 MB (fits in L2)
__device__ float g_P[CHUNKS * B_ * H_];
__device__ float g_S[CHUNKS * B_ * H_];
__device__ float g_carry[CHUNKS * B_ * H_];

// ================= helpers =================
__device__ __forceinline__ uint32_t smem_u32(const void* p) {
    uint32_t a;
    asm("{ .reg .u64 t; cvta.to.shared.u64 t, %1; cvt.u32.u64 %0, t; }" : "=r"(a) : "l"(p));
    return a;
}
// swizzle for 64-byte rows: chunk bits [5:4] ^= row bits (off bits [8:7])
__device__ __forceinline__ uint32_t swz(uint32_t off) {
    return off ^ ((off >> 3) & 0x30);
}
__device__ __forceinline__ void cp_async16(uint32_t dst, const void* src, int srcsize) {
    asm volatile("cp.async.cg.shared.global [%0], [%1], 16, %2;"
        :: "r"(dst), "l"(src), "r"(srcsize) : "memory");
}
__device__ __forceinline__ void ldsm_x4(uint32_t* r, uint32_t addr) {
    asm volatile("ldmatrix.sync.aligned.m8n8.x4.shared.b16 {%0,%1,%2,%3}, [%4];"
        : "=r"(r[0]), "=r"(r[1]), "=r"(r[2]), "=r"(r[3]) : "r"(addr));
}
__device__ __forceinline__ void mma_f16(float* c, const uint32_t* a, uint32_t b0, uint32_t b1) {
    asm volatile(
        "mma.sync.aligned.m16n8k16.row.col.f32.f16.f16.f32 "
        "{%0,%1,%2,%3}, {%4,%5,%6,%7}, {%8,%9}, {%0,%1,%2,%3};"
        : "+f"(c[0]), "+f"(c[1]), "+f"(c[2]), "+f"(c[3])
        : "r"(a[0]), "r"(a[1]), "r"(a[2]), "r"(a[3]), "r"(b0), "r"(b1));
}

// ---------------- X -> fp16 prepass ----------------
__global__ void convert_x(const float* __restrict__ X) {
    const int g = blockIdx.x * blockDim.x + threadIdx.x;   // M_*I_/8 threads
    const size_t base = (size_t)g * 8;
    float4 v0 = *(const float4*)(X + base);
    float4 v1 = *(const float4*)(X + base + 4);
    __half2 h[4];
    h[0] = __floats2half2_rn(v0.x, v0.y);
    h[1] = __floats2half2_rn(v0.z, v0.w);
    h[2] = __floats2half2_rn(v1.x, v1.y);
    h[3] = __floats2half2_rn(v1.z, v1.w);
    *(uint4*)(g_xh + base) = *(uint4*)h;
}

// ---------------- weight packing: Bmath[n][tap*512+i] halfs ----------------
__global__ void pack_weights(const float* __restrict__ Wz, const float* __restrict__ bz,
                             const float* __restrict__ Wf, const float* __restrict__ bf) {
    int idx = blockIdx.x * blockDim.x + threadIdx.x;
    if (idx >= ND_ * KD_) return;
    int n = idx >> 10;
    int k = idx & (KD_ - 1);
    int tap = k >> 9;          // tap0 -> x[t-1], tap1 -> x[t]
    int i = k & (I_ - 1);
    int h = n & (H_ - 1);
    const float* W = (n < H_) ? Wf : Wz;
    g_bmath[idx] = __float2half_rn(W[h * (I_ * 2) + i * 2 + tap]);
    if (k == 0) g_bias[n] = (n < H_) ? bf[n] : bz[n - H_];
}

// ---------------- fp16 mma.sync GEMM (shared-window A) -> half ----------------
// Output row m = m0+r:  raw[m] = X[m-1] . W_tap0 + X[m] . W_tap1
// smem A rows 0..128 hold X[m0-1 .. m0+127]; tap0 uses row r, tap1 row r+1.
// Row 0 zeroed when m0 is a sequence start (t=0 has no x[t-1] term).
__global__ __launch_bounds__(256, 2) void gemm_tc() {
    extern __shared__ char smem_raw[];
    const uint32_t raw_b = smem_u32(smem_raw);
    const uint32_t sbase = (raw_b + 127u) & ~127u;

    const int tid  = threadIdx.x;
    const int lane = tid & 31;
    const int wid  = tid >> 5;
    const int wm   = wid >> 2;       // 0..1 -> 64-row half
    const int wn   = wid & 3;        // 0..3 -> 32-col quarter
    const int n0   = blockIdx.x * BN;
    const int m0   = blockIdx.y * BM;

    // ---- A loader: row r = tid>>1 (0..127), two adjacent 16B chunks ----
    const int a_row = tid >> 1;
    const int a_c0  = (tid & 1) * 2;
    const uint32_t a_off0 = swz((uint32_t)(a_row * 64 + a_c0 * 16));
    const uint32_t a_off1 = swz((uint32_t)(a_row * 64 + (a_c0 + 1) * 16));
    const __half* aSrc = g_xh + (ptrdiff_t)(m0 - 1 + a_row) * I_ + a_c0 * 8;
    const bool zrow = ((m0 & (T_ - 1)) == 0) && (a_row == 0);
    // extra row 128 (X[m0+127]): threads 0..3 take chunk tid
    const uint32_t a_offX = swz((uint32_t)(128 * 64 + (tid & 3) * 16));
    const __half* aSrcX = g_xh + (ptrdiff_t)(m0 + 127) * I_ + (tid & 3) * 8;

    // ---- B loader: smem row q = tid (0..255) = tap*128 + n_local; 4 chunks ----
    const int b_tap = tid >> 7;
    const int b_n   = tid & 127;
    const uint32_t b_roff = (uint32_t)(tid * 64);
    const __half* bSrc = g_bmath + (size_t)(n0 + b_n) * KD_ + b_tap * I_;

    // ---- ldmatrix address params (m16n8k16 canonical fragments) ----
    const uint32_t a_cx  = (uint32_t)(((lane & 15) >> 1) & 3);            // row%8 bits [2:1]
    const uint32_t a_cx1 = (uint32_t)(((((lane & 7) + 1) & 7) >> 1) & 3); // (row+1)%8 bits [2:1]
    const uint32_t a_hi  = (uint32_t)(lane >> 4);
    uint32_t a_rowterm[4];
    #pragma unroll
    for (int mt = 0; mt < 4; mt++)
        a_rowterm[mt] = (uint32_t)((wm * 64 + mt * 16 + (lane & 15)) * 64);
    const uint32_t b_cx = (uint32_t)(((lane & 7) >> 1) & 3);
    const uint32_t b_hi = (uint32_t)((lane >> 3) & 1);
    uint32_t b_rowterm[2];
    #pragma unroll
    for (int p = 0; p < 2; p++)
        b_rowterm[p] = (uint32_t)((wn * 32 + p * 16 + ((lane >> 4) & 1) * 8 + (lane & 7)) * 64);

    float acc[4][4][4];
    #pragma unroll
    for (int mt = 0; mt < 4; mt++)
        #pragma unroll
        for (int nt = 0; nt < 4; nt++)
            #pragma unroll
            for (int q = 0; q < 4; q++) acc[mt][nt][q] = 0.f;

    // ---- producer: one stage = A window rows 0..128 + B both taps, 32 k ----
    auto issue = [&](int kt) {
        const uint32_t ab = sbase + (uint32_t)((kt & 3) * STG_BYTES);
        const uint32_t bb = ab + STG_A;
        const __half* ap = aSrc + kt * BK;
        cp_async16(ab + a_off0, zrow ? (const void*)g_xh : (const void*)ap,       zrow ? 0 : 16);
        cp_async16(ab + a_off1, zrow ? (const void*)g_xh : (const void*)(ap + 8), zrow ? 0 : 16);
        if (tid < 4)
            cp_async16(ab + a_offX, aSrcX + kt * BK, 16);
        const __half* bp = bSrc + kt * BK;
        #pragma unroll
        for (int c = 0; c < 4; c++)
            cp_async16(bb + swz(b_roff + c * 16), bp + c * 8, 16);
        asm volatile("cp.async.commit_group;" ::: "memory");
    };

    issue(0); issue(1); issue(2);

    #pragma unroll 1
    for (int kt = 0; kt < NKT; kt++) {
        if (kt < NKT - 2)       asm volatile("cp.async.wait_group 2;" ::: "memory");
        else if (kt == NKT - 2) asm volatile("cp.async.wait_group 1;" ::: "memory");
        else                    asm volatile("cp.async.wait_group 0;" ::: "memory");
        __syncthreads();
        if (kt + 3 < NKT) issue(kt + 3);

        const uint32_t ab  = sbase + (uint32_t)((kt & 3) * STG_BYTES);
        const uint32_t bb0 = ab + STG_A;          // tap0 B rows
        const uint32_t bb1 = bb0 + 128 * 64;      // tap1 B rows
        #pragma unroll
        for (int kh = 0; kh < 2; kh++) {
            const uint32_t ch = (uint32_t)(2 * kh) + a_hi;
            const uint32_t bh = (uint32_t)(2 * kh) + b_hi;
            uint32_t afr[4][4], bfr[2][4];
            // ---- tap0: A rows r, B tap0 ----
            #pragma unroll
            for (int mt = 0; mt < 4; mt++)
                ldsm_x4(afr[mt], ab + a_rowterm[mt] + ((ch ^ a_cx) << 4));
            #pragma unroll
            for (int p = 0; p < 2; p++)
                ldsm_x4(bfr[p], bb0 + b_rowterm[p] + ((bh ^ b_cx) << 4));
            #pragma unroll
            for (int mt = 0; mt < 4; mt++)
                #pragma unroll
                for (int nt = 0; nt < 4; nt++)
                    mma_f16(acc[mt][nt], afr[mt],
                            bfr[nt >> 1][(nt & 1) * 2], bfr[nt >> 1][(nt & 1) * 2 + 1]);
            // ---- tap1: A rows r+1 (+64B, re-swizzled), B tap1 ----
            #pragma unroll
            for (int mt = 0; mt < 4; mt++)
                ldsm_x4(afr[mt], ab + a_rowterm[mt] + 64 + ((ch ^ a_cx1) << 4));
            #pragma unroll
            for (int p = 0; p < 2; p++)
                ldsm_x4(bfr[p], bb1 + b_rowterm[p] + ((bh ^ b_cx) << 4));
            #pragma unroll
            for (int mt = 0; mt < 4; mt++)
                #pragma unroll
                for (int nt = 0; nt < 4; nt++)
                    mma_f16(acc[mt][nt], afr[mt],
                            bfr[nt >> 1][(nt & 1) * 2], bfr[nt >> 1][(nt & 1) * 2 + 1]);
        }
    }

    // ---- epilogue: convert to half, store (bias added in scan) ----
    #pragma unroll
    for (int mt = 0; mt < 4; mt++) {
        const int r0g = m0 + wm * 64 + mt * 16 + (lane >> 2);
        #pragma unroll
        for (int nt = 0; nt < 4; nt++) {
            const int col = n0 + wn * 32 + nt * 8 + (lane & 3) * 2;
            __half2 h0 = __floats2half2_rn(acc[mt][nt][0], acc[mt][nt][1]);
            __half2 h1 = __floats2half2_rn(acc[mt][nt][2], acc[mt][nt][3]);
            *(__half2*)(g_rawh + (size_t)r0g * ND_ + col)       = h0;
            *(__half2*)(g_rawh + (size_t)(r0g + 8) * ND_ + col) = h1;
        }
    }
}

// ---------------- scan: h[t] = f*h[t-1] + (1-f)*z  (bias folded in here) -------
__device__ __forceinline__ float sigmoidf_(float x) {
    return __fdividef(1.0f, 1.0f + __expf(-x));
}

// phase 1: per-(b,chunk,h-pair) — product of f and local state with zero init
__global__ void scan_p1() {
    const int g = blockIdx.x * blockDim.x + threadIdx.x;  // 131072 threads
    const int hh = (g & 255) * 2;
    const int bc = g >> 8;
    const int b = bc & (B_ - 1);
    const int cch = bc >> 5;
    const size_t m = (size_t)b * T_ + (size_t)cch * CLEN;
    const __half* pf = g_rawh + m * ND_ + hh;
    const float2 bf2 = *(const float2*)(g_bias + hh);
    const float2 bz2 = *(const float2*)(g_bias + hh + H_);
    float s0 = 0.f, s1 = 0.f, P0 = 1.f, P1 = 1.f;
    #pragma unroll 4
    for (int t = 0; t < CLEN; t++) {
        float2 rf = __half22float2(*(const __half2*)(pf + (size_t)t * ND_));
        float2 rz = __half22float2(*(const __half2*)(pf + (size_t)t * ND_ + H_));
        float f0 = sigmoidf_(rf.x + bf2.x), f1 = sigmoidf_(rf.y + bf2.y);
        float z0 = sigmoidf_(rz.x + bz2.x), z1 = sigmoidf_(rz.y + bz2.y);
        s0 = fmaf(f0, s0, (1.f - f0) * z0);
        s1 = fmaf(f1, s1, (1.f - f1) * z1);
        P0 *= f0; P1 *= f1;
    }
    const int idx = (cch * B_ + b) * H_ + hh;
    *(float2*)(g_P + idx) = make_float2(P0, P1);
    *(float2*)(g_S + idx) = make_float2(s0, s1);
}

// phase 2: per-(b,h) — sequential combine over chunks, record carry-in
__global__ void scan_p2() {
    const int g = blockIdx.x * blockDim.x + threadIdx.x;  // 16384 threads
    const int h = g & (H_ - 1);
    const int b = g >> 9;
    float carry = 0.f;
    #pragma unroll
    for (int cch = 0; cch < CHUNKS; cch++) {
        const int idx = (cch * B_ + b) * H_ + h;
        g_carry[idx] = carry;
        carry = fmaf(g_P[idx], carry, g_S[idx]);
    }
}

// phase 3: re-run with carry-in, write hidden
__global__ void scan_p3(float* __restrict__ out) {
    const int g = blockIdx.x * blockDim.x + threadIdx.x;  // 131072 threads
    const int hh = (g & 255) * 2;
    const int bc = g >> 8;
    const int b = bc & (B_ - 1);
    const int cch = bc >> 5;
    const size_t m = (size_t)b * T_ + (size_t)cch * CLEN;
    const __half* pf = g_rawh + m * ND_ + hh;
    float* po = out + m * H_ + hh;
    const float2 bf2 = *(const float2*)(g_bias + hh);
    const float2 bz2 = *(const float2*)(g_bias + hh + H_);
    float2 cr = *(const float2*)(g_carry + (cch * B_ + b) * H_ + hh);
    float s0 = cr.x, s1 = cr.y;
    #pragma unroll 4
    for (int t = 0; t < CLEN; t++) {
        float2 rf = __half22float2(*(const __half2*)(pf + (size_t)t * ND_));
        float2 rz = __half22float2(*(const __half2*)(pf + (size_t)t * ND_ + H_));
        float f0 = sigmoidf_(rf.x + bf2.x), f1 = sigmoidf_(rf.y + bf2.y);
        float z0 = sigmoidf_(rz.x + bz2.x), z1 = sigmoidf_(rz.y + bz2.y);
        s0 = fmaf(f0, s0, (1.f - f0) * z0);
        s1 = fmaf(f1, s1, (1.f - f1) * z1);
        *(float2*)(po + (size_t)t * H_) = make_float2(s0, s1);
    }
}

// ---------------- launch ----------------
extern "C" void kernel_launch(void* const* d_in, const int* in_sizes, int n_in,
                              void* d_out, int out_size) {
    const float* inputs = (const float*)d_in[0];
    const float* Wz = (const float*)d_in[2];
    const float* bz = (const float*)d_in[3];
    const float* Wf = (const float*)d_in[4];
    const float* bf = (const float*)d_in[5];
    float* out = (float*)d_out;

    convert_x<<<(M_ * I_ / 8 + 255) / 256, 256>>>(inputs);
    pack_weights<<<(ND_ * KD_ + 255) / 256, 256>>>(Wz, bz, Wf, bf);

    const int smem_need = STAGES * STG_BYTES + 128;   // ~97 KB + align slack
    cudaFuncSetAttribute(gemm_tc, cudaFuncAttributeMaxDynamicSharedMemorySize, smem_need);
    dim3 ggrid(ND_ / BN, M_ / BM);  // (8, 256)
    gemm_tc<<<ggrid, 256, smem_need>>>();

    scan_p1<<<(CHUNKS * B_ * 256) / 256, 256>>>();
    scan_p2<<<(B_ * H_) / 256, 256>>>();
    scan_p3<<<(CHUNKS * B_ * 256) / 256, 256>>>(out);
}

// round 16
// speedup vs baseline: 1.1089x; 1.1089x over previous
#include <cuda_runtime.h>
#include <cuda_fp16.h>
#include <cstdint>

// Problem constants
#define B_  32
#define T_  1024
#define I_  512
#define H_  512
#define M_  (B_*T_)          // 32768
#define KD_ 1024             // 2*I
#define ND_ 1024             // 2*H (n<512: f gate, n>=512: z gate)

#define CHUNKS 16
#define CLEN   (T_/CHUNKS)   // 64

// GEMM tiling (fp16): BK = 64 halfs = 128B rows, 3 stages
#define BM 128
#define BN 128
#define BK 64
#define STAGES 3
#define STG_A 16384          // 128 rows x 128B
#define STG_BYTES 32768      // A + B per stage
#define NKT (KD_/BK)         // 16 k-steps

// ---------------- scratch (static __device__, allocation-free) ----------------
__device__ __align__(128) __half g_bmath[ND_ * KD_];        // [n][k] halfs, 2 MB
__device__ __align__(128) __half g_xh[(size_t)M_ * I_];     // fp16 copy of X, 34 MB
__device__ float g_bias[ND_];
__device__ __align__(128) __half g_rawh[(size_t)M_ * ND_];  // 67 MB
__device__ float g_P[CHUNKS * B_ * H_];
__device__ float g_S[CHUNKS * B_ * H_];
__device__ float g_carry[CHUNKS * B_ * H_];

// ================= helpers =================
__device__ __forceinline__ uint32_t smem_u32(const void* p) {
    uint32_t a;
    asm("{ .reg .u64 t; cvta.to.shared.u64 t, %1; cvt.u32.u64 %0, t; }" : "=r"(a) : "l"(p));
    return a;
}
// SW128 swizzle for 128B rows: chunk bits [6:4] ^= row bits [2:0] (off bits [9:7])
__device__ __forceinline__ uint32_t swz128(uint32_t off) {
    return off ^ ((off >> 3) & 0x70);
}
__device__ __forceinline__ void cp_async16(uint32_t dst, const void* src, int srcsize) {
    asm volatile("cp.async.cg.shared.global [%0], [%1], 16, %2;"
        :: "r"(dst), "l"(src), "r"(srcsize) : "memory");
}
__device__ __forceinline__ void ldsm_x4(uint32_t* r, uint32_t addr) {
    asm volatile("ldmatrix.sync.aligned.m8n8.x4.shared.b16 {%0,%1,%2,%3}, [%4];"
        : "=r"(r[0]), "=r"(r[1]), "=r"(r[2]), "=r"(r[3]) : "r"(addr));
}
__device__ __forceinline__ void mma_f16(float* c, const uint32_t* a, uint32_t b0, uint32_t b1) {
    asm volatile(
        "mma.sync.aligned.m16n8k16.row.col.f32.f16.f16.f32 "
        "{%0,%1,%2,%3}, {%4,%5,%6,%7}, {%8,%9}, {%0,%1,%2,%3};"
        : "+f"(c[0]), "+f"(c[1]), "+f"(c[2]), "+f"(c[3])
        : "r"(a[0]), "r"(a[1]), "r"(a[2]), "r"(a[3]), "r"(b0), "r"(b1));
}

// ---------------- X -> fp16 prepass ----------------
__global__ void convert_x(const float* __restrict__ X) {
    const int g = blockIdx.x * blockDim.x + threadIdx.x;   // M_*I_/8 threads
    const size_t base = (size_t)g * 8;
    float4 v0 = *(const float4*)(X + base);
    float4 v1 = *(const float4*)(X + base + 4);
    __half2 h[4];
    h[0] = __floats2half2_rn(v0.x, v0.y);
    h[1] = __floats2half2_rn(v0.z, v0.w);
    h[2] = __floats2half2_rn(v1.x, v1.y);
    h[3] = __floats2half2_rn(v1.z, v1.w);
    *(uint4*)(g_xh + base) = *(uint4*)h;
}

// ---------------- weight packing: Bmath[n][k] halfs ----------------
__global__ void pack_weights(const float* __restrict__ Wz, const float* __restrict__ bz,
                             const float* __restrict__ Wf, const float* __restrict__ bf) {
    int idx = blockIdx.x * blockDim.x + threadIdx.x;
    if (idx >= ND_ * KD_) return;
    int n = idx >> 10;
    int k = idx & (KD_ - 1);
    int tap = k >> 9;          // k<512 -> tap0 (x[t-1]), k>=512 -> tap1 (x[t])
    int i = k & (I_ - 1);
    int h = n & (H_ - 1);
    const float* W = (n < H_) ? Wf : Wz;
    g_bmath[idx] = __float2half_rn(W[h * (I_ * 2) + i * 2 + tap]);
    if (k == 0) g_bias[n] = (n < H_) ? bf[n] : bz[n - H_];
}

// ---------------- fp16 mma.sync GEMM: raw = A * Bmath^T -> half (bias in scan) ----
// A[m,k] = Xh[(m-1)*512 + k]  (contiguous sliding window); zero when m%1024==0 && k<512.
__global__ __launch_bounds__(256, 2) void gemm_tc() {
    extern __shared__ char smem_raw[];
    const uint32_t raw_b = smem_u32(smem_raw);
    const uint32_t sbase = (raw_b + 127u) & ~127u;

    const int tid  = threadIdx.x;
    const int lane = tid & 31;
    const int wid  = tid >> 5;
    const int wm   = wid >> 2;       // 0..1 -> 64-row half
    const int wn   = wid & 3;        // 0..3 -> 32-col quarter
    const int n0   = blockIdx.x * BN;
    const int m0   = blockIdx.y * BM;

    // ---- global->smem load: one row, 4 ADJACENT 16B chunks per thread ----
    const int ldrow = tid >> 1;          // 0..127
    const int ldc0  = (tid & 1) * 4;     // chunk 0 or 4 (of 8 per 128B row)
    uint32_t ld_off[4];
    #pragma unroll
    for (int j = 0; j < 4; j++)
        ld_off[j] = swz128((uint32_t)(ldrow * 128 + (ldc0 + j) * 16));
    const __half* aSrc = g_xh + (ptrdiff_t)(m0 + ldrow - 1) * I_ + ldc0 * 8;
    const __half* bSrc = g_bmath + (size_t)(n0 + ldrow) * KD_ + ldc0 * 8;
    const bool zrow = ((m0 & (T_ - 1)) == 0) && (ldrow == 0);

    // ---- ldmatrix address params (m16n8k16 canonical fragments) ----
    const uint32_t cx   = (uint32_t)(lane & 7);        // row%8 for both A and B
    const uint32_t a_hi = (uint32_t)(lane >> 4);
    const uint32_t b_hi = (uint32_t)((lane >> 3) & 1);
    uint32_t a_rowterm[4];
    #pragma unroll
    for (int mt = 0; mt < 4; mt++)
        a_rowterm[mt] = (uint32_t)((wm * 64 + mt * 16 + (lane & 15)) * 128);
    uint32_t b_rowterm[2];
    #pragma unroll
    for (int p = 0; p < 2; p++)
        b_rowterm[p] = (uint32_t)((wn * 32 + p * 16 + ((lane >> 4) & 1) * 8 + (lane & 7)) * 128);

    float acc[4][4][4];
    #pragma unroll
    for (int mt = 0; mt < 4; mt++)
        #pragma unroll
        for (int nt = 0; nt < 4; nt++)
            #pragma unroll
            for (int q = 0; q < 4; q++) acc[mt][nt][q] = 0.f;

    // ---- producer ----
    auto issue = [&](int kt) {
        const uint32_t ab = sbase + (uint32_t)((kt % 3) * STG_BYTES);
        const uint32_t bb = ab + STG_A;
        const bool zz = zrow && (kt < 8);   // k = kt*64 .. < 512
        const __half* ap = aSrc + kt * BK;
        const __half* bp = bSrc + kt * BK;
        #pragma unroll
        for (int j = 0; j < 4; j++) {
            cp_async16(ab + ld_off[j], zz ? (const void*)g_xh : (const void*)(ap + j * 8),
                       zz ? 0 : 16);
            cp_async16(bb + ld_off[j], bp + j * 8, 16);
        }
        asm volatile("cp.async.commit_group;" ::: "memory");
    };

    issue(0); issue(1);

    #pragma unroll 1
    for (int kt = 0; kt < NKT; kt++) {
        if (kt < NKT - 1) asm volatile("cp.async.wait_group 1;" ::: "memory");
        else              asm volatile("cp.async.wait_group 0;" ::: "memory");
        __syncthreads();
        if (kt + 2 < NKT) issue(kt + 2);

        const uint32_t ab = sbase + (uint32_t)((kt % 3) * STG_BYTES);
        const uint32_t bb = ab + STG_A;
        #pragma unroll
        for (int kh = 0; kh < 4; kh++) {
            uint32_t afr[4][4], bfr[2][4];
            #pragma unroll
            for (int mt = 0; mt < 4; mt++)
                ldsm_x4(afr[mt], ab + a_rowterm[mt]
                                 + ((((uint32_t)(2 * kh) + a_hi) ^ cx) << 4));
            #pragma unroll
            for (int p = 0; p < 2; p++)
                ldsm_x4(bfr[p], bb + b_rowterm[p]
                                 + ((((uint32_t)(2 * kh) + b_hi) ^ cx) << 4));
            #pragma unroll
            for (int mt = 0; mt < 4; mt++)
                #pragma unroll
                for (int nt = 0; nt < 4; nt++)
                    mma_f16(acc[mt][nt], afr[mt],
                            bfr[nt >> 1][(nt & 1) * 2], bfr[nt >> 1][(nt & 1) * 2 + 1]);
        }
    }

    // ---- epilogue: convert to half, store (bias added in scan) ----
    #pragma unroll
    for (int mt = 0; mt < 4; mt++) {
        const int r0g = m0 + wm * 64 + mt * 16 + (lane >> 2);
        #pragma unroll
        for (int nt = 0; nt < 4; nt++) {
            const int col = n0 + wn * 32 + nt * 8 + (lane & 3) * 2;
            __half2 h0 = __floats2half2_rn(acc[mt][nt][0], acc[mt][nt][1]);
            __half2 h1 = __floats2half2_rn(acc[mt][nt][2], acc[mt][nt][3]);
            *(__half2*)(g_rawh + (size_t)r0g * ND_ + col)       = h0;
            *(__half2*)(g_rawh + (size_t)(r0g + 8) * ND_ + col) = h1;
        }
    }
}

// ---------------- scan: h[t] = f*h[t-1] + (1-f)*z  (bias folded in here) -------
__device__ __forceinline__ float sigmoidf_(float x) {
    return __fdividef(1.0f, 1.0f + __expf(-x));
}

// phase 1: per-(b,chunk,h-pair) — product of f and local state with zero init
__global__ void scan_p1() {
    const int g = blockIdx.x * blockDim.x + threadIdx.x;  // 131072 threads
    const int hh = (g & 255) * 2;
    const int bc = g >> 8;
    const int b = bc & (B_ - 1);
    const int cch = bc >> 5;
    const size_t m = (size_t)b * T_ + (size_t)cch * CLEN;
    const __half* pf = g_rawh + m * ND_ + hh;
    const float2 bf2 = *(const float2*)(g_bias + hh);
    const float2 bz2 = *(const float2*)(g_bias + hh + H_);
    float s0 = 0.f, s1 = 0.f, P0 = 1.f, P1 = 1.f;
    #pragma unroll 4
    for (int t = 0; t < CLEN; t++) {
        float2 rf = __half22float2(*(const __half2*)(pf + (size_t)t * ND_));
        float2 rz = __half22float2(*(const __half2*)(pf + (size_t)t * ND_ + H_));
        float f0 = sigmoidf_(rf.x + bf2.x), f1 = sigmoidf_(rf.y + bf2.y);
        float z0 = sigmoidf_(rz.x + bz2.x), z1 = sigmoidf_(rz.y + bz2.y);
        s0 = fmaf(f0, s0, (1.f - f0) * z0);
        s1 = fmaf(f1, s1, (1.f - f1) * z1);
        P0 *= f0; P1 *= f1;
    }
    const int idx = (cch * B_ + b) * H_ + hh;
    *(float2*)(g_P + idx) = make_float2(P0, P1);
    *(float2*)(g_S + idx) = make_float2(s0, s1);
}

// phase 2: per-(b,h) — sequential combine over chunks, record carry-in
__global__ void scan_p2() {
    const int g = blockIdx.x * blockDim.x + threadIdx.x;  // 16384 threads
    const int h = g & (H_ - 1);
    const int b = g >> 9;
    float carry = 0.f;
    #pragma unroll
    for (int cch = 0; cch < CHUNKS; cch++) {
        const int idx = (cch * B_ + b) * H_ + h;
        g_carry[idx] = carry;
        carry = fmaf(g_P[idx], carry, g_S[idx]);
    }
}

// phase 3: re-run with carry-in, write hidden
__global__ void scan_p3(float* __restrict__ out) {
    const int g = blockIdx.x * blockDim.x + threadIdx.x;  // 131072 threads
    const int hh = (g & 255) * 2;
    const int bc = g >> 8;
    const int b = bc & (B_ - 1);
    const int cch = bc >> 5;
    const size_t m = (size_t)b * T_ + (size_t)cch * CLEN;
    const __half* pf = g_rawh + m * ND_ + hh;
    float* po = out + m * H_ + hh;
    const float2 bf2 = *(const float2*)(g_bias + hh);
    const float2 bz2 = *(const float2*)(g_bias + hh + H_);
    float2 cr = *(const float2*)(g_carry + (cch * B_ + b) * H_ + hh);
    float s0 = cr.x, s1 = cr.y;
    #pragma unroll 4
    for (int t = 0; t < CLEN; t++) {
        float2 rf = __half22float2(*(const __half2*)(pf + (size_t)t * ND_));
        float2 rz = __half22float2(*(const __half2*)(pf + (size_t)t * ND_ + H_));
        float f0 = sigmoidf_(rf.x + bf2.x), f1 = sigmoidf_(rf.y + bf2.y);
        float z0 = sigmoidf_(rz.x + bz2.x), z1 = sigmoidf_(rz.y + bz2.y);
        s0 = fmaf(f0, s0, (1.f - f0) * z0);
        s1 = fmaf(f1, s1, (1.f - f1) * z1);
        *(float2*)(po + (size_t)t * H_) = make_float2(s0, s1);
    }
}

// ---------------- launch ----------------
extern "C" void kernel_launch(void* const* d_in, const int* in_sizes, int n_in,
                              void* d_out, int out_size) {
    const float* inputs = (const float*)d_in[0];
    const float* Wz = (const float*)d_in[2];
    const float* bz = (const float*)d_in[3];
    const float* Wf = (const float*)d_in[4];
    const float* bf = (const float*)d_in[5];
    float* out = (float*)d_out;

    convert_x<<<(M_ * I_ / 8 + 255) / 256, 256>>>(inputs);
    pack_weights<<<(ND_ * KD_ + 255) / 256, 256>>>(Wz, bz, Wf, bf);

    const int smem_need = STAGES * STG_BYTES + 128;   // 96 KB + align slack
    cudaFuncSetAttribute(gemm_tc, cudaFuncAttributeMaxDynamicSharedMemorySize, smem_need);
    dim3 ggrid(ND_ / BN, M_ / BM);  // (8, 256)
    gemm_tc<<<ggrid, 256, smem_need>>>();

    scan_p1<<<(CHUNKS * B_ * 256) / 256, 256>>>();
    scan_p2<<<(B_ * H_) / 256, 256>>>();
    scan_p3<<<(CHUNKS * B_ * 256) / 256, 256>>>(out);
}

// round 17
// speedup vs baseline: 1.1544x; 1.0410x over previous
#include <cuda_runtime.h>
#include <cuda_fp16.h>
#include <cstdint>

// Problem constants
#define B_  32
#define T_  1024
#define I_  512
#define H_  512
#define M_  (B_*T_)          // 32768
#define KD_ 1024             // 2*I
#define ND_ 1024             // 2*H (n<512: f gate, n>=512: z gate)

#define CHUNKS 32
#define CLEN   (T_/CHUNKS)   // 32

// GEMM tiling (fp16, R10 proven): BK = 32 halfs = 64B rows, 4 stages
#define BM 128
#define BN 128
#define BK 32
#define STAGES 4
#define STG_A 8192           // 128 rows x 64B
#define STG_BYTES 16384      // A + B per stage
#define NKT (KD_/BK)         // 32 k-steps

// ---------------- scratch (static __device__, allocation-free) ----------------
__device__ __align__(128) __half g_bmath[ND_ * KD_];        // [n][k] halfs, 2 MB
__device__ __align__(128) __half g_xh[(size_t)M_ * I_];     // fp16 copy of X, 34 MB
__device__ float g_bias[ND_];
__device__ __align__(128) __half g_rawh[(size_t)M_ * ND_];  // 67 MB (fits in L2)
__device__ float g_P[CHUNKS * B_ * H_];
__device__ float g_S[CHUNKS * B_ * H_];
__device__ float g_carry[CHUNKS * B_ * H_];

// ================= helpers =================
__device__ __forceinline__ uint32_t smem_u32(const void* p) {
    uint32_t a;
    asm("{ .reg .u64 t; cvta.to.shared.u64 t, %1; cvt.u32.u64 %0, t; }" : "=r"(a) : "l"(p));
    return a;
}
// swizzle for 64-byte rows: chunk bits [5:4] ^= row bits (off bits [8:7])
__device__ __forceinline__ uint32_t swz(uint32_t off) {
    return off ^ ((off >> 3) & 0x30);
}
__device__ __forceinline__ void cp_async16(uint32_t dst, const void* src, int srcsize) {
    asm volatile("cp.async.cg.shared.global [%0], [%1], 16, %2;"
        :: "r"(dst), "l"(src), "r"(srcsize) : "memory");
}
__device__ __forceinline__ void ldsm_x4(uint32_t* r, uint32_t addr) {
    asm volatile("ldmatrix.sync.aligned.m8n8.x4.shared.b16 {%0,%1,%2,%3}, [%4];"
        : "=r"(r[0]), "=r"(r[1]), "=r"(r[2]), "=r"(r[3]) : "r"(addr));
}
__device__ __forceinline__ void mma_f16(float* c, const uint32_t* a, uint32_t b0, uint32_t b1) {
    asm volatile(
        "mma.sync.aligned.m16n8k16.row.col.f32.f16.f16.f32 "
        "{%0,%1,%2,%3}, {%4,%5,%6,%7}, {%8,%9}, {%0,%1,%2,%3};"
        : "+f"(c[0]), "+f"(c[1]), "+f"(c[2]), "+f"(c[3])
        : "r"(a[0]), "r"(a[1]), "r"(a[2]), "r"(a[3]), "r"(b0), "r"(b1));
}

// ---------------- X -> fp16 prepass ----------------
__global__ void convert_x(const float* __restrict__ X) {
    const int g = blockIdx.x * blockDim.x + threadIdx.x;   // M_*I_/8 threads
    const size_t base = (size_t)g * 8;
    float4 v0 = *(const float4*)(X + base);
    float4 v1 = *(const float4*)(X + base + 4);
    __half2 h[4];
    h[0] = __floats2half2_rn(v0.x, v0.y);
    h[1] = __floats2half2_rn(v0.z, v0.w);
    h[2] = __floats2half2_rn(v1.x, v1.y);
    h[3] = __floats2half2_rn(v1.z, v1.w);
    *(uint4*)(g_xh + base) = *(uint4*)h;
}

// ---------------- weight packing: Bmath[n][k] halfs ----------------
__global__ void pack_weights(const float* __restrict__ Wz, const float* __restrict__ bz,
                             const float* __restrict__ Wf, const float* __restrict__ bf) {
    int idx = blockIdx.x * blockDim.x + threadIdx.x;
    if (idx >= ND_ * KD_) return;
    int n = idx >> 10;
    int k = idx & (KD_ - 1);
    int tap = k >> 9;          // k<512 -> tap0 (x[t-1]), k>=512 -> tap1 (x[t])
    int i = k & (I_ - 1);
    int h = n & (H_ - 1);
    const float* W = (n < H_) ? Wf : Wz;
    g_bmath[idx] = __float2half_rn(W[h * (I_ * 2) + i * 2 + tap]);
    if (k == 0) g_bias[n] = (n < H_) ? bf[n] : bz[n - H_];
}

// ---------------- fp16 mma.sync GEMM: raw = A * Bmath^T -> half (bias in scan) ----
// A[m,k] = Xh[(m-1)*512 + k]  (contiguous sliding window); zero when m%1024==0 && k<512.
__global__ __launch_bounds__(256, 2) void gemm_tc() {
    extern __shared__ char smem_raw[];
    const uint32_t raw_b = smem_u32(smem_raw);
    const uint32_t sbase = (raw_b + 127u) & ~127u;

    const int tid  = threadIdx.x;
    const int lane = tid & 31;
    const int wid  = tid >> 5;
    const int wm   = wid >> 2;       // 0..1 -> 64-row half
    const int wn   = wid & 3;        // 0..3 -> 32-col quarter
    const int n0   = blockIdx.x * BN;
    const int m0   = blockIdx.y * BM;

    // ---- global->smem load: one row, two ADJACENT 16B chunks per thread ----
    const int ldrow = tid >> 1;          // 0..127
    const int ldc0  = (tid & 1) * 2;     // chunk 0 or 2 (of 4 per 64B row)
    const uint32_t ld_off0 = swz((uint32_t)(ldrow * 64 + ldc0 * 16));
    const uint32_t ld_off1 = swz((uint32_t)(ldrow * 64 + (ldc0 + 1) * 16));
    const __half* aSrc = g_xh + (ptrdiff_t)(m0 + ldrow - 1) * I_ + ldc0 * 8;
    const __half* bSrc = g_bmath + (size_t)(n0 + ldrow) * KD_ + ldc0 * 8;
    const bool zrow = ((m0 & (T_ - 1)) == 0) && (ldrow == 0);

    // ---- ldmatrix address params (m16n8k16 canonical fragments) ----
    const uint32_t a_cx = (uint32_t)(((lane & 15) >> 1) & 3);
    const uint32_t a_hi = (uint32_t)(lane >> 4);
    uint32_t a_rowterm[4];
    #pragma unroll
    for (int mt = 0; mt < 4; mt++)
        a_rowterm[mt] = (uint32_t)((wm * 64 + mt * 16 + (lane & 15)) * 64);
    const uint32_t b_cx = (uint32_t)(((lane & 7) >> 1) & 3);
    const uint32_t b_hi = (uint32_t)((lane >> 3) & 1);
    uint32_t b_rowterm[2];
    #pragma unroll
    for (int p = 0; p < 2; p++)
        b_rowterm[p] = (uint32_t)((wn * 32 + p * 16 + ((lane >> 4) & 1) * 8 + (lane & 7)) * 64);

    float acc[4][4][4];
    #pragma unroll
    for (int mt = 0; mt < 4; mt++)
        #pragma unroll
        for (int nt = 0; nt < 4; nt++)
            #pragma unroll
            for (int q = 0; q < 4; q++) acc[mt][nt][q] = 0.f;

    // ---- producer ----
    auto issue = [&](int kt) {
        const uint32_t ab = sbase + (uint32_t)((kt & 3) * STG_BYTES);
        const uint32_t bb = ab + STG_A;
        const bool zz = zrow && (kt < 16);   // k = kt*32 .. < 512
        const __half* ap = aSrc + kt * BK;
        const __half* bp = bSrc + kt * BK;
        cp_async16(ab + ld_off0, zz ? (const void*)g_xh : (const void*)ap,       zz ? 0 : 16);
        cp_async16(ab + ld_off1, zz ? (const void*)g_xh : (const void*)(ap + 8), zz ? 0 : 16);
        cp_async16(bb + ld_off0, bp, 16);
        cp_async16(bb + ld_off1, bp + 8, 16);
        asm volatile("cp.async.commit_group;" ::: "memory");
    };

    issue(0); issue(1); issue(2);

    #pragma unroll 1
    for (int kt = 0; kt < NKT; kt++) {
        if (kt < NKT - 2)       asm volatile("cp.async.wait_group 2;" ::: "memory");
        else if (kt == NKT - 2) asm volatile("cp.async.wait_group 1;" ::: "memory");
        else                    asm volatile("cp.async.wait_group 0;" ::: "memory");
        __syncthreads();
        if (kt + 3 < NKT) issue(kt + 3);

        const uint32_t ab = sbase + (uint32_t)((kt & 3) * STG_BYTES);
        const uint32_t bb = ab + STG_A;
        #pragma unroll
        for (int kh = 0; kh < 2; kh++) {
            uint32_t afr[4][4], bfr[2][4];
            #pragma unroll
            for (int mt = 0; mt < 4; mt++)
                ldsm_x4(afr[mt], ab + a_rowterm[mt]
                                 + ((((uint32_t)(2 * kh) + a_hi) ^ a_cx) << 4));
            #pragma unroll
            for (int p = 0; p < 2; p++)
                ldsm_x4(bfr[p], bb + b_rowterm[p]
                                 + ((((uint32_t)(2 * kh) + b_hi) ^ b_cx) << 4));
            #pragma unroll
            for (int mt = 0; mt < 4; mt++)
                #pragma unroll
                for (int nt = 0; nt < 4; nt++)
                    mma_f16(acc[mt][nt], afr[mt],
                            bfr[nt >> 1][(nt & 1) * 2], bfr[nt >> 1][(nt & 1) * 2 + 1]);
        }
    }

    // ---- epilogue: convert to half, store (bias added in scan) ----
    #pragma unroll
    for (int mt = 0; mt < 4; mt++) {
        const int r0g = m0 + wm * 64 + mt * 16 + (lane >> 2);
        #pragma unroll
        for (int nt = 0; nt < 4; nt++) {
            const int col = n0 + wn * 32 + nt * 8 + (lane & 3) * 2;
            __half2 h0 = __floats2half2_rn(acc[mt][nt][0], acc[mt][nt][1]);
            __half2 h1 = __floats2half2_rn(acc[mt][nt][2], acc[mt][nt][3]);
            *(__half2*)(g_rawh + (size_t)r0g * ND_ + col)       = h0;
            *(__half2*)(g_rawh + (size_t)(r0g + 8) * ND_ + col) = h1;
        }
    }
}

// ---------------- scan: h[t] = f*h[t-1] + (1-f)*z  (bias folded in here) -------
__device__ __forceinline__ float sigmoidf_(float x) {
    return __fdividef(1.0f, 1.0f + __expf(-x));
}

// phase 1: per-(b,chunk,h-pair) — product of f and local state with zero init
__global__ void scan_p1() {
    const int g = blockIdx.x * blockDim.x + threadIdx.x;  // 262144 threads
    const int hh = (g & 255) * 2;
    const int bc = g >> 8;
    const int b = bc & (B_ - 1);
    const int cch = bc >> 5;
    const size_t m = (size_t)b * T_ + (size_t)cch * CLEN;
    const __half* pf = g_rawh + m * ND_ + hh;
    const float2 bf2 = *(const float2*)(g_bias + hh);
    const float2 bz2 = *(const float2*)(g_bias + hh + H_);
    float s0 = 0.f, s1 = 0.f, P0 = 1.f, P1 = 1.f;
    #pragma unroll 4
    for (int t = 0; t < CLEN; t++) {
        float2 rf = __half22float2(*(const __half2*)(pf + (size_t)t * ND_));
        float2 rz = __half22float2(*(const __half2*)(pf + (size_t)t * ND_ + H_));
        float f0 = sigmoidf_(rf.x + bf2.x), f1 = sigmoidf_(rf.y + bf2.y);
        float z0 = sigmoidf_(rz.x + bz2.x), z1 = sigmoidf_(rz.y + bz2.y);
        s0 = fmaf(f0, s0, (1.f - f0) * z0);
        s1 = fmaf(f1, s1, (1.f - f1) * z1);
        P0 *= f0; P1 *= f1;
    }
    const int idx = (cch * B_ + b) * H_ + hh;
    *(float2*)(g_P + idx) = make_float2(P0, P1);
    *(float2*)(g_S + idx) = make_float2(s0, s1);
}

// phase 2: per-(b,h) — sequential combine over chunks, record carry-in
__global__ void scan_p2() {
    const int g = blockIdx.x * blockDim.x + threadIdx.x;  // 16384 threads
    const int h = g & (H_ - 1);
    const int b = g >> 9;
    float carry = 0.f;
    #pragma unroll
    for (int cch = 0; cch < CHUNKS; cch++) {
        const int idx = (cch * B_ + b) * H_ + h;
        g_carry[idx] = carry;
        carry = fmaf(g_P[idx], carry, g_S[idx]);
    }
}

// phase 3: re-run with carry-in, write hidden
__global__ void scan_p3(float* __restrict__ out) {
    const int g = blockIdx.x * blockDim.x + threadIdx.x;  // 262144 threads
    const int hh = (g & 255) * 2;
    const int bc = g >> 8;
    const int b = bc & (B_ - 1);
    const int cch = bc >> 5;
    const size_t m = (size_t)b * T_ + (size_t)cch * CLEN;
    const __half* pf = g_rawh + m * ND_ + hh;
    float* po = out + m * H_ + hh;
    const float2 bf2 = *(const float2*)(g_bias + hh);
    const float2 bz2 = *(const float2*)(g_bias + hh + H_);
    float2 cr = *(const float2*)(g_carry + (cch * B_ + b) * H_ + hh);
    float s0 = cr.x, s1 = cr.y;
    #pragma unroll 4
    for (int t = 0; t < CLEN; t++) {
        float2 rf = __half22float2(*(const __half2*)(pf + (size_t)t * ND_));
        float2 rz = __half22float2(*(const __half2*)(pf + (size_t)t * ND_ + H_));
        float f0 = sigmoidf_(rf.x + bf2.x), f1 = sigmoidf_(rf.y + bf2.y);
        float z0 = sigmoidf_(rz.x + bz2.x), z1 = sigmoidf_(rz.y + bz2.y);
        s0 = fmaf(f0, s0, (1.f - f0) * z0);
        s1 = fmaf(f1, s1, (1.f - f1) * z1);
        *(float2*)(po + (size_t)t * H_) = make_float2(s0, s1);
    }
}

// ---------------- launch ----------------
extern "C" void kernel_launch(void* const* d_in, const int* in_sizes, int n_in,
                              void* d_out, int out_size) {
    const float* inputs = (const float*)d_in[0];
    const float* Wz = (const float*)d_in[2];
    const float* bz = (const float*)d_in[3];
    const float* Wf = (const float*)d_in[4];
    const float* bf = (const float*)d_in[5];
    float* out = (float*)d_out;

    convert_x<<<(M_ * I_ / 8 + 255) / 256, 256>>>(inputs);
    pack_weights<<<(ND_ * KD_ + 255) / 256, 256>>>(Wz, bz, Wf, bf);

    const int smem_need = STAGES * STG_BYTES + 128;   // 64 KB + align slack
    cudaFuncSetAttribute(gemm_tc, cudaFuncAttributeMaxDynamicSharedMemorySize, smem_need);
    dim3 ggrid(ND_ / BN, M_ / BM);  // (8, 256)
    gemm_tc<<<ggrid, 256, smem_need>>>();

    scan_p1<<<(CHUNKS * B_ * 256) / 256, 256>>>();
    scan_p2<<<(B_ * H_) / 256, 256>>>();
    scan_p3<<<(CHUNKS * B_ * 256) / 256, 256>>>(out);
}